// round 11
// baseline (speedup 1.0000x reference)
#include <cuda_runtime.h>
#include <cuda_bf16.h>

// SurvivalGeometryRegularizer:
//   mask[i][j] = (time[i] < time[j]) && (event[i] == 1)
//   hinge      = relu(1 + risk[i] - risk[j])
//   out        = sum(mask*hinge) / sum(mask)   (0 if count==0)
// z (d_in[0]) is UNUSED. Inputs: [1]=risk f32[B], [2]=time f32[B], [3]=event i32[B].
//
// R11: ONE cooperative kernel (592 blocks = one resident wave; <=4/SM needed),
// spin grid-syncs replace R10's three serialized launches (~15us of overhead).
//   Phase A: blocks 0-31 bucket histogram (b = floor(t*256), exact in f32)
//   Phase B: block 0 exclusive scan -> bucket starts + (bucket,block) offsets
//   Phase C: blocks 0-31 deterministic stable scatter into bucket order
//   Phase D: all blocks: 74 i-tiles x 8 j-chunks(1024).
//     Tile bucket span [b_first,b_last]; LO=bstart[b_first], HI=bstart[b_last+1].
//     j >= HI  => t_i < t_j EXACTLY (bucket bound) -> no compare, no count.
//     j in [LO,HI) -> exact-compare region, STAGED IN SMEM (chunk-clamped,
//     width <= 1024), counted there. Suffix count analytic: ne*(B-HI).
//   Last-block ticket finalize; all sums fixed-order -> deterministic.
//   g_sync/g_ticket reset by finalize block -> graph-replay safe.

#define BN     8192
#define TPB    256
#define NBUCK  256
#define NBLK_H 32                 // histogram/scatter work blocks
#define ISPL   74
#define JCH    8
#define CWIDE  1024               // j-chunk width
#define NPART  (ISPL * JCH)       // 592 = one full wave
#define MAXROW 128
#define MAXBW  1024               // boundary width (chunk-clamped, guaranteed)

#define PINF __int_as_float(0x7f800000)
#define NINF __int_as_float(0xff800000)

__device__ unsigned int g_cnt[NBUCK * NBLK_H];
__device__ int          g_bstart[NBUCK + 1];
__device__ float        g_st[BN];
__device__ float        g_sr[BN];
__device__ int          g_sev[BN];
__device__ float        g_ps[NPART];
__device__ float        g_pc[NPART];
__device__ unsigned int g_ticket;   // zero-init; finalize resets
__device__ unsigned int g_sync;     // zero-init; finalize resets

__device__ __forceinline__ void grid_sync(unsigned int target)
{
    __syncthreads();
    if (threadIdx.x == 0) {
        __threadfence();
        atomicAdd(&g_sync, 1u);
        while (*((volatile unsigned int*)&g_sync) < target) { }
        __threadfence();
    }
    __syncthreads();
}

__global__ __launch_bounds__(TPB, 4) void fused_all_kernel(
    const float* __restrict__ risk,
    const float* __restrict__ time_,
    const int*   __restrict__ event,
    float*       __restrict__ out)
{
    __shared__ unsigned int  sh_cnt[NBUCK];       // phase A
    __shared__ unsigned char sh_cw[8][NBUCK];     // phase C
    __shared__ float2        s_i[MAXROW];         // phase D: events (t_i, 1+r_i)
    __shared__ float         s_bt[MAXBW];         // boundary t_j
    __shared__ float         s_bnr[MAXBW];        // boundary -r_j
    __shared__ int           s_wsum[TPB / 32];
    __shared__ int           s_lne, s_bf, s_bl;
    __shared__ float         s_rs[TPB / 32], s_rc[TPB / 32];
    __shared__ int           s_islast;
    __shared__ double        f_s[TPB / 32], f_c[TPB / 32];

    const int tid  = threadIdx.x;
    const int lane = tid & 31;
    const int wid  = tid >> 5;
    const int bx   = blockIdx.x;              // i-tile (74)
    const int sc   = blockIdx.y;              // j-chunk (8)
    const int flat = sc * ISPL + bx;          // 0..591

    // ================= Phase A: histogram (blocks 0..31) =================
    if (flat < NBLK_H) {
        sh_cnt[tid] = 0;
        __syncthreads();
        const int idx = flat * TPB + tid;
        const int b = (int)(time_[idx] * 256.0f);   // exact: pow2 scale
        atomicAdd(&sh_cnt[b], 1u);
        __syncthreads();
        g_cnt[tid * NBLK_H + flat] = sh_cnt[tid];
    }
    grid_sync(NPART);

    // ================= Phase B: scan (block 0, 256 thr) ==================
    if (flat == 0) {
        const int b = tid;
        unsigned int row[NBLK_H];
        unsigned int sum = 0;
        #pragma unroll
        for (int k = 0; k < NBLK_H; k++) {
            const unsigned int t = g_cnt[b * NBLK_H + k];
            row[k] = sum;
            sum += t;
        }
        unsigned int incl = sum;
        #pragma unroll
        for (int o = 1; o < 32; o <<= 1) {
            unsigned int y = __shfl_up_sync(0xffffffffu, incl, o);
            if (lane >= o) incl += y;
        }
        if (lane == 31) s_wsum[wid] = (int)incl;
        __syncthreads();
        if (wid == 0) {
            unsigned int x = (lane < 8) ? (unsigned int)s_wsum[lane] : 0u;
            unsigned int xi = x;
            #pragma unroll
            for (int o = 1; o < 8; o <<= 1) {
                unsigned int y = __shfl_up_sync(0xffffffffu, xi, o);
                if (lane >= o) xi += y;
            }
            if (lane < 8) s_wsum[lane] = (int)(xi - x);  // exclusive warp bases
        }
        __syncthreads();
        const unsigned int base = (unsigned int)s_wsum[wid] + incl - sum;
        g_bstart[b] = (int)base;
        if (b == NBUCK - 1) g_bstart[NBUCK] = BN;
        #pragma unroll
        for (int k = 0; k < NBLK_H; k++)
            g_cnt[b * NBLK_H + k] = base + row[k];
    }
    grid_sync(2 * NPART);

    // ================= Phase C: stable scatter (blocks 0..31) ============
    if (flat < NBLK_H) {
        for (int k = tid; k < 8 * NBUCK; k += TPB) (&sh_cw[0][0])[k] = 0;
        __syncthreads();
        const int idx = flat * TPB + tid;
        const float t = time_[idx];
        const float r = risk[idx];
        const int   e = event[idx];
        const int   b = (int)(t * 256.0f);
        const unsigned int peers = __match_any_sync(0xffffffffu, b);
        const int wrank  = __popc(peers & ((1u << lane) - 1u));
        const int leader = __ffs(peers) - 1;
        if (lane == leader) sh_cw[wid][b] = (unsigned char)__popc(peers);
        __syncthreads();
        int rank = wrank;
        for (int w = 0; w < wid; w++) rank += sh_cw[w][b];
        const int pos = (int)g_cnt[b * NBLK_H + flat] + rank;
        g_st[pos]  = t;
        g_sr[pos]  = r;
        g_sev[pos] = e;
    }
    grid_sync(3 * NPART);

    // ================= Phase D: main pairwise ============================
    const int ilo  = (bx * BN) / ISPL;
    const int ihi  = ((bx + 1) * BN) / ISPL;
    const int rows = ihi - ilo;               // 110 or 111

    const int   inr = tid < rows;
    const int   p   = ilo + tid;
    const float ti  = inr ? g_st[p] : 0.0f;
    const int   ev  = inr ? g_sev[p] : 0;
    const float ai  = inr ? (1.0f + g_sr[p]) : 0.0f;

    if (tid == 0)        s_bf = (int)(ti * 256.0f);
    if (tid == rows - 1) s_bl = (int)(ti * 256.0f);

    // event compaction into s_i
    int incl = ev;
    #pragma unroll
    for (int o = 1; o < 32; o <<= 1) {
        int y = __shfl_up_sync(0xffffffffu, incl, o);
        if (lane >= o) incl += y;
    }
    if (lane == 31) s_wsum[wid] = incl;
    __syncthreads();
    if (wid == 0) {
        int v = (lane < TPB / 32) ? s_wsum[lane] : 0;
        #pragma unroll
        for (int o = 1; o < TPB / 32; o <<= 1) {
            int y = __shfl_up_sync(0xffffffffu, v, o);
            if (lane >= o) v += y;
        }
        if (lane < TPB / 32) s_wsum[lane] = v;
        if (lane == TPB / 32 - 1) s_lne = v;
    }
    __syncthreads();
    {
        const int base = (wid ? s_wsum[wid - 1] : 0) + (incl - ev);
        if (ev) s_i[base] = make_float2(ti, ai);
    }
    __syncthreads();

    const int ne     = s_lne;
    const int ne_pad = (ne + 3) & ~3;
    if (tid < ne_pad - ne)
        s_i[ne + tid] = make_float2(PINF, NINF);   // a=-inf -> relu 0
    const int LO = g_bstart[s_bf];
    const int HI = g_bstart[s_bl + 1];
    __syncthreads();

    const int j0 = sc * CWIDE;

    float ss0 = 0.0f, ss1 = 0.0f;
    float cc  = 0.0f;
    if (sc == JCH - 1 && tid == 0)
        cc = (float)ne * (float)(BN - HI);         // analytic suffix count

    // ---- no-compare region: chunk ∩ [HI, BN) -----------------------------
    if (HI < j0 + CWIDE) {
        float nr0, nr1, nr2, nr3;
        int j;
        j = j0 + 0 * TPB + tid; nr0 = (j >= HI) ? -g_sr[j] : NINF;
        j = j0 + 1 * TPB + tid; nr1 = (j >= HI) ? -g_sr[j] : NINF;
        j = j0 + 2 * TPB + tid; nr2 = (j >= HI) ? -g_sr[j] : NINF;
        j = j0 + 3 * TPB + tid; nr3 = (j >= HI) ? -g_sr[j] : NINF;

        for (int k = 0; k < ne_pad; k += 4) {
            #pragma unroll
            for (int u = 0; u < 4; u++) {
                const float a = s_i[k + u].y;      // broadcast LDS
                ss0 += fmaxf(a + nr0, 0.0f);
                ss1 += fmaxf(a + nr1, 0.0f);
                ss0 += fmaxf(a + nr2, 0.0f);
                ss1 += fmaxf(a + nr3, 0.0f);
            }
        }
    }

    // ---- compare region: chunk ∩ [LO, HI), staged in smem ----------------
    {
        const int lo_c = (LO > j0) ? LO : j0;
        const int hi_c = (HI < j0 + CWIDE) ? HI : (j0 + CWIDE);
        const int w = hi_c - lo_c;                 // <= CWIDE <= MAXBW
        if (w > 0) {
            for (int k = tid; k < w; k += TPB) {
                s_bt[k]  = g_st[lo_c + k];
                s_bnr[k] = -g_sr[lo_c + k];
            }
            __syncthreads();
            for (int ii = wid; ii < ne; ii += TPB / 32) {
                const float2 e = s_i[ii];
                for (int jj = lane; jj < w; jj += 32) {
                    if (e.x < s_bt[jj]) {          // exact strict compare
                        ss0 += fmaxf(e.y + s_bnr[jj], 0.0f);
                        cc  += 1.0f;
                    }
                }
            }
        }
    }

    float ss = ss0 + ss1;

    // ---- deterministic intra-block reduction -----------------------------
    #pragma unroll
    for (int o = 16; o > 0; o >>= 1) {
        ss += __shfl_down_sync(0xffffffffu, ss, o);
        cc += __shfl_down_sync(0xffffffffu, cc, o);
    }
    if (lane == 0) { s_rs[wid] = ss; s_rc[wid] = cc; }
    __syncthreads();
    if (tid == 0) {
        float sv = 0.0f, cv = 0.0f;
        #pragma unroll
        for (int w = 0; w < TPB / 32; w++) { sv += s_rs[w]; cv += s_rc[w]; }
        g_ps[flat] = sv;
        g_pc[flat] = cv;
    }

    // ---- last-block fused finalize ---------------------------------------
    __threadfence();
    if (tid == 0) {
        const unsigned int t = atomicAdd(&g_ticket, 1u);
        s_islast = (t == NPART - 1) ? 1 : 0;
    }
    __syncthreads();

    if (s_islast) {
        __threadfence();
        double sv = 0.0, cv = 0.0;
        for (int idx = tid; idx < NPART; idx += TPB) {   // fixed order
            sv += (double)g_ps[idx];
            cv += (double)g_pc[idx];
        }
        #pragma unroll
        for (int o = 16; o > 0; o >>= 1) {
            sv += __shfl_down_sync(0xffffffffu, sv, o);
            cv += __shfl_down_sync(0xffffffffu, cv, o);
        }
        if (lane == 0) { f_s[wid] = sv; f_c[wid] = cv; }
        __syncthreads();
        if (tid == 0) {
            double ts = 0.0, tc = 0.0;
            #pragma unroll
            for (int w = 0; w < TPB / 32; w++) { ts += f_s[w]; tc += f_c[w]; }
            out[0] = (tc != 0.0) ? (float)(ts / tc) : 0.0f;
            g_ticket = 0;                  // graph-replay safe
            g_sync   = 0;
        }
    }
}

extern "C" void kernel_launch(void* const* d_in, const int* in_sizes, int n_in,
                              void* d_out, int out_size)
{
    // d_in[0] = z (unused)
    const float* risk  = (const float*)d_in[1];
    const float* time_ = (const float*)d_in[2];
    const int*   event = (const int*)d_in[3];

    fused_all_kernel<<<dim3(ISPL, JCH), TPB>>>(risk, time_, event, (float*)d_out);
}

// round 13
// speedup vs baseline: 1.5403x; 1.5403x over previous
#include <cuda_runtime.h>
#include <cuda_bf16.h>

// SurvivalGeometryRegularizer:
//   mask[i][j] = (time[i] < time[j]) && (event[i] == 1)
//   hinge      = relu(1 + risk[i] - risk[j])
//   out        = sum(mask*hinge) / sum(mask)   (0 if count==0)
// z (d_in[0]) is UNUSED. Inputs: [1]=risk f32[B], [2]=time f32[B], [3]=event i32[B].
//
// R12: block-LOCAL bucket decomposition -- zero global prep, ONE launch.
// Block (i-tile bx of ~110 rows, j-chunk sc of 1024 cols):
//   - tile events bucketed by b = floor(t*32) (exact pow2) into smem arrays
//     s_ia (a=1+r, bucket-grouped) + prefix s_epre[33]; deterministic
//     __match_any rank scatter (verified machinery from R10).
//   - the block's 1024 j's grouped by the same buckets into s_j (same
//     deterministic scatter, 4 subphases) so each warp's 32 j's share a bucket.
//   - per j (bucket d): events in buckets < d  =>  t_i < t_j EXACTLY
//     (t_i < (c+1)/32 <= d/32 <= t_j)  ->  sum loop with NO compare, NO
//     per-pair count (count += epre[d]); same-bucket events (~2) use the
//     exact strict-compare path. Warp-uniform unroll via __reduce_min_sync.
//   - last-block ticket finalize, fixed-order sums -> deterministic.

#define BN    8192
#define TPB   256
#define ISPL  74
#define JCH   8
#define CWID  1024
#define NPART (ISPL * JCH)        // 592 blocks = one wave (4/SM)
#define NLB   32                  // local time buckets

__device__ float        g_ps[NPART];
__device__ float        g_pc[NPART];
__device__ unsigned int g_ticket;   // zero-init at load; finalize resets

__global__ __launch_bounds__(TPB) void fused_kernel(
    const float* __restrict__ risk,
    const float* __restrict__ time_,
    const int*   __restrict__ event,
    float*       __restrict__ out)
{
    __shared__ float         s_ia[128];         // events' (1+r), bucket-grouped
    __shared__ float2        s_ie[128];         // events' (t, 1+r) for exact path
    __shared__ int           s_epre[NLB + 1];   // event bucket prefix
    __shared__ float         s_epref[NLB + 1];  // float copy (count adds)
    __shared__ float2        s_j[CWID];         // (t_j, -r_j), bucket-grouped
    __shared__ unsigned char s_icw[8][NLB];     // per-warp i-bucket counts
    __shared__ unsigned char s_jcw[4][8][NLB];  // per-(subphase,warp) j counts
    __shared__ int           s_jpre[NLB];
    __shared__ float         s_rs[8], s_rc[8];
    __shared__ int           s_islast;
    __shared__ double        f_s[8], f_c[8];

    const int tid  = threadIdx.x;
    const int lane = tid & 31;
    const int wid  = tid >> 5;
    const int bx   = blockIdx.x;
    const int sc   = blockIdx.y;
    const int flat = sc * ISPL + bx;

    // ---- i-slice (balanced 8192/74) --------------------------------------
    const int ilo  = (bx * BN) / ISPL;
    const int ihi  = ((bx + 1) * BN) / ISPL;
    const int rows = ihi - ilo;                 // 110 or 111

    const int   inr = tid < rows;
    const int   ii  = ilo + tid;
    const int   evf = inr ? event[ii] : 0;
    const float ti  = inr ? time_[ii] : 0.0f;
    const float ai  = inr ? (1.0f + risk[ii]) : 0.0f;
    const int   bi  = (int)(ti * 32.0f);        // exact pow2 bucketing

    // ---- this block's 1024 j's (coalesced) -------------------------------
    float tj[4], nrj[4];
    #pragma unroll
    for (int m = 0; m < 4; m++) {
        const int j = sc * CWID + m * TPB + tid;
        tj[m]  = time_[j];
        nrj[m] = -risk[j];
    }

    // ---- zero count tables ----------------------------------------------
    (&s_icw[0][0])[tid] = 0;
    #pragma unroll
    for (int q = 0; q < 4; q++) (&s_jcw[0][0][0])[q * TPB + tid] = 0;
    __syncthreads();

    // ---- histograms via __match_any (deterministic ranks) ----------------
    const int      ikey = (inr && evf) ? bi : (NLB + lane);  // dummies unique
    const unsigned ip   = __match_any_sync(0xffffffffu, ikey);
    const int      iwr  = __popc(ip & ((1u << lane) - 1u));
    const bool     isev = (inr && evf != 0);
    if (isev && iwr == 0) s_icw[wid][bi] = (unsigned char)__popc(ip);

    int jb[4], jwr[4];
    #pragma unroll
    for (int m = 0; m < 4; m++) {
        jb[m] = (int)(tj[m] * 32.0f);
        const unsigned p = __match_any_sync(0xffffffffu, jb[m]);
        jwr[m] = __popc(p & ((1u << lane) - 1u));
        if (jwr[m] == 0) s_jcw[m][wid][jb[m]] = (unsigned char)__popc(p);
    }
    __syncthreads();

    // ---- bucket scans (warp 0) -------------------------------------------
    if (tid < NLB) {
        const int b = tid;
        int itot = 0;
        #pragma unroll
        for (int w = 0; w < 8; w++) itot += s_icw[w][b];
        int incl = itot;
        #pragma unroll
        for (int o = 1; o < 32; o <<= 1) {
            const int y = __shfl_up_sync(0xffffffffu, incl, o);
            if (lane >= o) incl += y;
        }
        s_epre[b]  = incl - itot;
        s_epref[b] = (float)(incl - itot);
        if (b == NLB - 1) { s_epre[NLB] = incl; s_epref[NLB] = (float)incl; }

        int jtot = 0;
        #pragma unroll
        for (int m = 0; m < 4; m++)
            #pragma unroll
            for (int w = 0; w < 8; w++) jtot += s_jcw[m][w][b];
        int jincl = jtot;
        #pragma unroll
        for (int o = 1; o < 32; o <<= 1) {
            const int y = __shfl_up_sync(0xffffffffu, jincl, o);
            if (lane >= o) jincl += y;
        }
        s_jpre[b] = jincl - jtot;
    }
    __syncthreads();

    // ---- deterministic scatters ------------------------------------------
    if (isev) {
        int pos = s_epre[bi] + iwr;
        for (int w = 0; w < wid; w++) pos += s_icw[w][bi];
        s_ia[pos] = ai;
        s_ie[pos] = make_float2(ti, ai);
    }
    #pragma unroll
    for (int m = 0; m < 4; m++) {
        const int b = jb[m];
        int pos = s_jpre[b] + jwr[m];
        for (int mm = 0; mm < m; mm++) {
            #pragma unroll
            for (int w = 0; w < 8; w++) pos += s_jcw[mm][w][b];
        }
        for (int w = 0; w < wid; w++) pos += s_jcw[m][w][b];
        s_j[pos] = make_float2(tj[m], nrj[m]);
    }
    __syncthreads();

    // ---- main loops: compare-free prefix + tiny exact same-bucket --------
    float ss0 = 0.0f, ss1 = 0.0f, cc = 0.0f;
    #pragma unroll
    for (int m = 0; m < 4; m++) {
        const int    slot = wid * 128 + m * 32 + lane;  // warp-consecutive
        const float2 jv   = s_j[slot];
        const float  nr   = jv.y;
        const int    d    = (int)(jv.x * 32.0f);
        const int    E    = s_epre[d];                  // events below bucket d
        cc += s_epref[d];                               // their count, one add

        const int Emin = __reduce_min_sync(0xffffffffu, E);
        const int E4   = Emin & ~3;
        int k = 0;
        for (; k < E4; k += 4) {                        // warp-uniform, no cmp
            ss0 += fmaxf(s_ia[k]     + nr, 0.0f);
            ss1 += fmaxf(s_ia[k + 1] + nr, 0.0f);
            ss0 += fmaxf(s_ia[k + 2] + nr, 0.0f);
            ss1 += fmaxf(s_ia[k + 3] + nr, 0.0f);
        }
        for (; k < E; k++)                              // small remainder
            ss0 += fmaxf(s_ia[k] + nr, 0.0f);

        const int E2 = s_epre[d + 1];                   // same-bucket: exact
        for (; k < E2; k++) {
            const float2 e = s_ie[k];
            if (e.x < jv.x) {                           // strict, exact
                ss1 += fmaxf(e.y + nr, 0.0f);
                cc  += 1.0f;
            }
        }
    }
    float ss = ss0 + ss1;

    // ---- deterministic intra-block reduction -----------------------------
    #pragma unroll
    for (int o = 16; o > 0; o >>= 1) {
        ss += __shfl_down_sync(0xffffffffu, ss, o);
        cc += __shfl_down_sync(0xffffffffu, cc, o);
    }
    if (lane == 0) { s_rs[wid] = ss; s_rc[wid] = cc; }
    __syncthreads();
    if (tid == 0) {
        float sv = 0.0f, cv = 0.0f;
        #pragma unroll
        for (int w = 0; w < 8; w++) { sv += s_rs[w]; cv += s_rc[w]; }
        g_ps[flat] = sv;
        g_pc[flat] = cv;
    }

    // ---- last-block fused finalize (threadfence + ticket) ----------------
    __threadfence();
    if (tid == 0) {
        const unsigned int t = atomicAdd(&g_ticket, 1u);
        s_islast = (t == NPART - 1) ? 1 : 0;
    }
    __syncthreads();

    if (s_islast) {
        __threadfence();
        double sv = 0.0, cv = 0.0;
        for (int idx = tid; idx < NPART; idx += TPB) {   // fixed order
            sv += (double)g_ps[idx];
            cv += (double)g_pc[idx];
        }
        #pragma unroll
        for (int o = 16; o > 0; o >>= 1) {
            sv += __shfl_down_sync(0xffffffffu, sv, o);
            cv += __shfl_down_sync(0xffffffffu, cv, o);
        }
        if (lane == 0) { f_s[wid] = sv; f_c[wid] = cv; }
        __syncthreads();
        if (tid == 0) {
            double ts = 0.0, tc = 0.0;
            #pragma unroll
            for (int w = 0; w < 8; w++) { ts += f_s[w]; tc += f_c[w]; }
            out[0] = (tc != 0.0) ? (float)(ts / tc) : 0.0f;
            g_ticket = 0;                  // graph-replay safe
        }
    }
}

extern "C" void kernel_launch(void* const* d_in, const int* in_sizes, int n_in,
                              void* d_out, int out_size)
{
    // d_in[0] = z (unused)
    const float* risk  = (const float*)d_in[1];
    const float* time_ = (const float*)d_in[2];
    const int*   event = (const int*)d_in[3];

    fused_kernel<<<dim3(ISPL, JCH), TPB>>>(risk, time_, event, (float*)d_out);
}